// round 10
// baseline (speedup 1.0000x reference)
#include <cuda_runtime.h>
#include <cuda_fp16.h>
#include <cstdint>
#include <math.h>

#define BB 64
#define SS 512
#define II 256
#define HH 512
#define KTOT 768
#define G4 2048
#define KC 64
#define NCH 12                 // chunks 0-3 = x, 4-11 = h
#define NTILES 64
#define NCTAS 128

#define RSTRIDE 144            // padded row stride bytes (72 fp16)
// smem: [0,55296) W[12 ch][32 rows][72 fp16]
//       [55296,110592) A stages 3 x 18432 (A_hi 9216 + A_lo 9216)
//       [110592,119808) Gs
#define B_OFF    0
#define A_OFF    55296
#define A_STAGE  18432
#define GS_OFF   110592
#define SMEM_DYN 119808

// ---------------- persistent device state ----------------
__device__ float g_c[2 * BB * HH];
__device__ __align__(16) __half g_h_hi[2 * 2 * BB * HH];   // [dir][parity][b][n]
__device__ __align__(16) __half g_h_lo[2 * 2 * BB * HH];
__device__ __align__(16) __half g_x_hi[(size_t)BB * SS * II];
__device__ __align__(16) __half g_x_lo[(size_t)BB * SS * II];
__device__ __align__(16) __half g_wt[(size_t)2 * G4 * KTOT];  // [dir][prow][k]
__device__ __align__(16) float g_bias_p[2 * G4];
__device__ float g_hb[(size_t)BB * SS * HH];
// x-part gates (+bias), [dir][tile][t][b][32 cols] fp32
__device__ float g_gx[(size_t)2 * NTILES * SS * BB * 32];
__device__ unsigned g_bar_count;
__device__ volatile unsigned g_bar_epoch;

// ---------------- helpers ----------------
__device__ __forceinline__ uint32_t smem_u32(const void* p) {
    uint32_t a;
    asm("{ .reg .u64 t; cvta.to.shared.u64 t, %1; cvt.u32.u64 %0, t; }" : "=r"(a) : "l"(p));
    return a;
}
__device__ __forceinline__ void cp16(uint32_t dst, const void* src) {
    asm volatile("cp.async.cg.shared.global [%0], [%1], 16;" :: "r"(dst), "l"(src));
}
__device__ __forceinline__ void cp_commit() { asm volatile("cp.async.commit_group;"); }
__device__ __forceinline__ void cp_wait0()  { asm volatile("cp.async.wait_group 0;"); }
__device__ __forceinline__ void cp_wait1()  { asm volatile("cp.async.wait_group 1;"); }

__device__ __forceinline__ void ldm_x4(uint32_t* r, uint32_t addr) {
    asm volatile("ldmatrix.sync.aligned.m8n8.x4.shared.b16 {%0,%1,%2,%3}, [%4];"
                 : "=r"(r[0]), "=r"(r[1]), "=r"(r[2]), "=r"(r[3]) : "r"(addr));
}
__device__ __forceinline__ void ldm_x2(uint32_t* r, uint32_t addr) {
    asm volatile("ldmatrix.sync.aligned.m8n8.x2.shared.b16 {%0,%1}, [%2];"
                 : "=r"(r[0]), "=r"(r[1]) : "r"(addr));
}
__device__ __forceinline__ void mma16816(float* c, const uint32_t* a, const uint32_t* b) {
    asm volatile("mma.sync.aligned.m16n8k16.row.col.f32.f16.f16.f32 "
                 "{%0,%1,%2,%3}, {%4,%5,%6,%7}, {%8,%9}, {%0,%1,%2,%3};"
                 : "+f"(c[0]), "+f"(c[1]), "+f"(c[2]), "+f"(c[3])
                 : "r"(a[0]), "r"(a[1]), "r"(a[2]), "r"(a[3]), "r"(b[0]), "r"(b[1]));
}

// ---------------- prep kernels ----------------
__global__ void zero_state_kernel() {
    int idx = blockIdx.x * blockDim.x + threadIdx.x;
    if (idx < 2 * 2 * BB * HH) {
        g_h_hi[idx] = __float2half(0.f);
        g_h_lo[idx] = __float2half(0.f);
    }
    if (idx < 2 * BB * HH) g_c[idx] = 0.0f;
    if (idx == 0) { g_bar_count = 0u; g_bar_epoch = 0u; }
}

__global__ void prep_x_kernel(const float* __restrict__ x) {
    size_t i = (size_t)blockIdx.x * blockDim.x + threadIdx.x;
    if (i >= (size_t)BB * SS * II) return;
    float v = x[i];
    __half h = __float2half_rn(v);
    g_x_hi[i] = h;
    g_x_lo[i] = __float2half_rn(v - __half2float(h));
}

// W[k][gc] -> Wt[dir][prow = j*4+gate][k], gc = gate*512 + j  (single fp16)
__global__ void prep_w_kernel(const float* __restrict__ W_f, const float* __restrict__ W_b) {
    int idx = blockIdx.x * blockDim.x + threadIdx.x;
    if (idx >= 2 * KTOT * G4) return;
    int dir = idx / (KTOT * G4);
    int rem = idx % (KTOT * G4);
    int k  = rem / G4;
    int gc = rem % G4;
    float w = (dir ? W_b : W_f)[rem];
    int gate = gc >> 9;
    int j    = gc & 511;
    int prow = j * 4 + gate;
    g_wt[((size_t)dir * G4 + prow) * KTOT + k] = __float2half_rn(w);
}

__global__ void prep_bias_kernel(const float* __restrict__ b_f, const float* __restrict__ b_b) {
    int idx = blockIdx.x * blockDim.x + threadIdx.x;
    if (idx >= 2 * G4) return;
    int dir = idx / G4;
    int gc  = idx % G4;
    int gate = gc >> 9, j = gc & 511;
    g_bias_p[dir * G4 + j * 4 + gate] = (dir ? b_b : b_f)[gc];
}

// ---------------- A-stage loader (activations hi+lo) ----------------
__device__ __forceinline__ void load_A(uint32_t smb, int stage, int ch,
                                       int tid, int dir, int p, int tx) {
    uint32_t base = smb + A_OFF + stage * A_STAGE;
    const int k0 = ch * KC;
#pragma unroll
    for (int i = 0; i < 2; i++) {
        int idx = tid + i * 256;
        int r = idx >> 3, q = idx & 7;
        uint32_t doff = r * RSTRIDE + q * 16;
        const __half *sh, *sl;
        if (k0 < II) {
            size_t so = ((size_t)r * SS + tx) * II + k0 + q * 8;
            sh = g_x_hi + so; sl = g_x_lo + so;
        } else {
            size_t so = ((size_t)(dir * 2 + p) * BB + r) * HH + (k0 - II) + q * 8;
            sh = g_h_hi + so; sl = g_h_lo + so;
        }
        cp16(base + doff, sh);
        cp16(base + 9216 + doff, sl);
    }
    cp_commit();
}

// ---------------- chunk compute: 2-term fp16 (16 MMAs/warp) ----------------
__device__ __forceinline__ void compute_chunk(uint32_t smb, int stage, int ch,
                                              int lane, int wm, int wn,
                                              float accH[2][4], float accX[2][4]) {
    const uint32_t Ab = smb + A_OFF + stage * A_STAGE;
    const uint32_t Bb = smb + B_OFF + (uint32_t)ch * 4608;
#pragma unroll
    for (int ks = 0; ks < 4; ks++) {
        uint32_t ah[4], al[4], bh[2][2];
        uint32_t ad = Ab + (uint32_t)(wm * 16 + (lane & 15)) * RSTRIDE
                         + (uint32_t)(ks * 16 + (lane >> 4) * 8) * 2;
        ldm_x4(ah, ad);
        ldm_x4(al, ad + 9216);
#pragma unroll
        for (int nt = 0; nt < 2; nt++) {
            uint32_t boff = (uint32_t)(wn * 16 + nt * 8 + (lane & 7)) * RSTRIDE
                          + (uint32_t)(ks * 16 + ((lane >> 3) & 1) * 8) * 2;
            ldm_x2(bh[nt], Bb + boff);
        }
#pragma unroll
        for (int nt = 0; nt < 2; nt++) {
            mma16816(accH[nt], ah, bh[nt]);   // hi chain
            mma16816(accX[nt], al, bh[nt]);   // lo-correction chain
        }
    }
}

// ---------------- persistent kernel ----------------
__global__ void __launch_bounds__(256, 1) lstm_persistent(float* __restrict__ out) {
    extern __shared__ __align__(16) char sm[];
    const int tid  = threadIdx.x;
    const int lane = tid & 31;
    const int wid  = tid >> 5;
    const int wm   = wid & 3;
    const int wn   = wid >> 2;
    const int tile = blockIdx.x;
    const int dir  = blockIdx.y;
    const int n0 = tile * 32;
    const int j0 = tile * 8;
    const uint32_t smb = smem_u32(sm);

    const int frow = wm * 16 + (lane >> 2);
    const int fc0  = wn * 16 + 0 * 8 + 2 * (lane & 3);
    const int fc1  = wn * 16 + 1 * 8 + 2 * (lane & 3);

    // ---- all 12 weight chunks resident in smem (single fp16) ----
    for (int u = tid; u < NCH * 32 * 8; u += 256) {
        int ch = u >> 8;
        int rem = u & 255;
        int r = rem >> 3, q = rem & 7;
        size_t so = ((size_t)dir * G4 + n0 + r) * KTOT + ch * KC + q * 8;
        uint32_t doff = (uint32_t)ch * 4608 + r * RSTRIDE + q * 16;
        cp16(smb + B_OFF + doff, g_wt + so);
    }
    cp_commit();
    cp_wait0();
    __syncthreads();

    float2 bv0 = make_float2(g_bias_p[dir * G4 + n0 + fc0],
                             g_bias_p[dir * G4 + n0 + fc0 + 1]);
    float2 bv1 = make_float2(g_bias_p[dir * G4 + n0 + fc1],
                             g_bias_p[dir * G4 + n0 + fc1 + 1]);

    float* gx_cta = g_gx + ((size_t)(dir * NTILES + tile) * SS) * BB * 32;

    // ============ PHASE 1: x-part gates for all t (no barriers) ============
    {
        float accH[2][4], accX[2][4];
#pragma unroll
        for (int nt = 0; nt < 2; nt++)
#pragma unroll
            for (int i = 0; i < 4; i++) { accH[nt][i] = 0.f; accX[nt][i] = 0.f; }

        const int NFL = SS * 4;
        load_A(smb, 0, 0, tid, dir, 0, 0);
        load_A(smb, 1, 1, tid, dir, 0, 0);
#pragma unroll 1
        for (int fl = 0; fl < NFL; fl++) {
            const int tt = fl >> 2, ch = fl & 3;
            if (fl == NFL - 1) cp_wait0(); else cp_wait1();
            __syncthreads();
            if (fl + 2 < NFL) {
                int f2 = fl + 2;
                load_A(smb, f2 % 3, f2 & 3, tid, dir, 0, f2 >> 2);
            }
            compute_chunk(smb, fl % 3, ch, lane, wm, wn, accH, accX);
            if (ch == 3) {
                float* gxt = gx_cta + (size_t)tt * (BB * 32);
                *(float2*)&gxt[frow * 32 + fc0] =
                    make_float2(accH[0][0] + accX[0][0] + bv0.x, accH[0][1] + accX[0][1] + bv0.y);
                *(float2*)&gxt[(frow + 8) * 32 + fc0] =
                    make_float2(accH[0][2] + accX[0][2] + bv0.x, accH[0][3] + accX[0][3] + bv0.y);
                *(float2*)&gxt[frow * 32 + fc1] =
                    make_float2(accH[1][0] + accX[1][0] + bv1.x, accH[1][1] + accX[1][1] + bv1.y);
                *(float2*)&gxt[(frow + 8) * 32 + fc1] =
                    make_float2(accH[1][2] + accX[1][2] + bv1.x, accH[1][3] + accX[1][3] + bv1.y);
#pragma unroll
                for (int nt = 0; nt < 2; nt++)
#pragma unroll
                    for (int i = 0; i < 4; i++) { accH[nt][i] = 0.f; accX[nt][i] = 0.f; }
            }
        }
    }

    // ============ PHASE 2: 512-step recurrence, 8 h-chunks per step ============
#pragma unroll 1
    for (int t = 0; t < SS; t++) {
        const int tx = dir ? (SS - 1 - t) : t;
        const int p  = t & 1;

        const float* gxt = gx_cta + (size_t)tx * (BB * 32);
        float2 s00 = *(const float2*)&gxt[frow * 32 + fc0];
        float2 s01 = *(const float2*)&gxt[(frow + 8) * 32 + fc0];
        float2 s10 = *(const float2*)&gxt[frow * 32 + fc1];
        float2 s11 = *(const float2*)&gxt[(frow + 8) * 32 + fc1];

        if (t > 0) {
            if (tid == 0) {
                while (g_bar_epoch < (unsigned)t) {}
                __threadfence();
            }
            __syncthreads();
        }

        float accH[2][4], accX[2][4];
        accH[0][0] = s00.x; accH[0][1] = s00.y; accH[0][2] = s01.x; accH[0][3] = s01.y;
        accH[1][0] = s10.x; accH[1][1] = s10.y; accH[1][2] = s11.x; accH[1][3] = s11.y;
#pragma unroll
        for (int nt = 0; nt < 2; nt++)
#pragma unroll
            for (int i = 0; i < 4; i++) accX[nt][i] = 0.f;

        load_A(smb, 0, 4, tid, dir, p, tx);
        load_A(smb, 1, 5, tid, dir, p, tx);
#pragma unroll 1
        for (int hc = 0; hc < 8; hc++) {
            if (hc == 7) cp_wait0(); else cp_wait1();
            __syncthreads();
            if (hc + 2 < 8) load_A(smb, (hc + 2) % 3, 6 + hc, tid, dir, p, tx);
            compute_chunk(smb, hc % 3, 4 + hc, lane, wm, wn, accH, accX);
        }

        // ---- epilogue: gates to smem ----
        float* Gs = (float*)(sm + GS_OFF);   // [64][36]
        {
            int col0 = wn * 16 + 2 * (lane & 3);
            *(float2*)&Gs[frow * 36 + col0] =
                make_float2(accH[0][0] + accX[0][0], accH[0][1] + accX[0][1]);
            *(float2*)&Gs[(frow + 8) * 36 + col0] =
                make_float2(accH[0][2] + accX[0][2], accH[0][3] + accX[0][3]);
            *(float2*)&Gs[frow * 36 + col0 + 8] =
                make_float2(accH[1][0] + accX[1][0], accH[1][1] + accX[1][1]);
            *(float2*)&Gs[(frow + 8) * 36 + col0 + 8] =
                make_float2(accH[1][2] + accX[1][2], accH[1][3] + accX[1][3]);
        }
        __syncthreads();

        // ---- pointwise LSTM update (bias already in gx) ----
#pragma unroll
        for (int r2 = 0; r2 < 2; r2++) {
            int e = tid + r2 * 256;
            int b = e & 63;
            int jl = e >> 6;
            float4 g = *(float4*)&Gs[b * 36 + jl * 4];
            float fs = 1.0f / (1.0f + __expf(-g.x));
            float is = 1.0f / (1.0f + __expf(-g.y));
            float os = 1.0f / (1.0f + __expf(-g.z));
            int n = j0 + jl;
            float cprev = g_c[(dir * BB + b) * HH + n];
            float cn = fs * cprev + is * tanhf(g.w);
            float hn = os * tanhf(cn);
            g_c[(dir * BB + b) * HH + n] = cn;
            size_t hidx = ((size_t)(dir * 2 + (1 - p)) * BB + b) * HH + n;
            __half hh = __float2half_rn(hn);
            g_h_hi[hidx] = hh;
            g_h_lo[hidx] = __float2half_rn(hn - __half2float(hh));
            size_t oi = ((size_t)b * SS + tx) * HH + n;
            if (dir == 0) out[oi]  = 0.5f * hn;
            else          g_hb[oi] = 0.5f * hn;
        }

        // ---- barrier ARRIVE ----
        __syncthreads();
        if (t < SS - 1 && tid == 0) {
            __threadfence();
            unsigned n = atomicAdd(&g_bar_count, 1u);
            if (n == NCTAS - 1u) {
                g_bar_count = 0u;
                __threadfence();
                g_bar_epoch = (unsigned)(t + 1);
            }
        }
    }
}

// out = 0.5*hf + 0.5*hb
__global__ void combine_kernel(float* __restrict__ out) {
    size_t i = (size_t)blockIdx.x * blockDim.x + threadIdx.x;
    const size_t n4 = (size_t)BB * SS * HH / 4;
    if (i < n4) {
        float4 a = ((const float4*)out)[i];
        float4 b = ((const float4*)g_hb)[i];
        a.x += b.x; a.y += b.y; a.z += b.z; a.w += b.w;
        ((float4*)out)[i] = a;
    }
}

extern "C" void kernel_launch(void* const* d_in, const int* in_sizes, int n_in,
                              void* d_out, int out_size) {
    const float* x   = (const float*)d_in[0];
    const float* W_f = (const float*)d_in[1];
    const float* b_f = (const float*)d_in[2];
    const float* W_b = (const float*)d_in[3];
    const float* b_b = (const float*)d_in[4];
    float* out = (float*)d_out;

    cudaFuncSetAttribute((const void*)lstm_persistent,
                         cudaFuncAttributeMaxDynamicSharedMemorySize, SMEM_DYN);

    zero_state_kernel<<<512, 256>>>();
    {
        size_t nx = (size_t)BB * SS * II;
        prep_x_kernel<<<(unsigned)((nx + 255) / 256), 256>>>(x);
    }
    prep_w_kernel<<<(2 * KTOT * G4 + 255) / 256, 256>>>(W_f, W_b);
    prep_bias_kernel<<<(2 * G4 + 255) / 256, 256>>>(b_f, b_b);

    dim3 grid(NTILES, 2);
    lstm_persistent<<<grid, 256, SMEM_DYN>>>(out);

    const int n4 = BB * SS * HH / 4;
    combine_kernel<<<(n4 + 255) / 256, 256>>>(out);
}

// round 11
// speedup vs baseline: 1.0177x; 1.0177x over previous
#include <cuda_runtime.h>
#include <cuda_fp16.h>
#include <cstdint>
#include <math.h>

#define BB 64
#define SS 512
#define II 256
#define HH 512
#define KTOT 768
#define G4 2048
#define KC 64
#define NCH 12                 // chunks 0-3 = x, 4-11 = h
#define NTILES 64
#define NCTA_DIR 64            // CTAs per direction

#define RSTRIDE 144            // padded row stride bytes (72 fp16)
#define A_BUF 18432            // one chunk buffer (A_hi 9216 + A_lo 9216)
// smem: [0,55296) W[12 ch][32 rows][72 fp16]
//       [55296, 55296+8*18432) 8 dedicated A chunk buffers
//       [202752, 211968) Gs
#define B_OFF    0
#define A_OFF    55296
#define GS_OFF   202752
#define SMEM_DYN 211968

// ---------------- persistent device state ----------------
__device__ float g_c[2 * BB * HH];
__device__ __align__(16) __half g_h_hi[2 * 2 * BB * HH];   // [dir][parity][b][n]
__device__ __align__(16) __half g_h_lo[2 * 2 * BB * HH];
__device__ __align__(16) __half g_x_hi[(size_t)BB * SS * II];
__device__ __align__(16) __half g_x_lo[(size_t)BB * SS * II];
__device__ __align__(16) __half g_wt[(size_t)2 * G4 * KTOT];  // [dir][prow][k]
__device__ __align__(16) float g_bias_p[2 * G4];
__device__ float g_hb[(size_t)BB * SS * HH];
__device__ float g_gx[(size_t)2 * NTILES * SS * BB * 32];  // x-part gates (+bias)
__device__ unsigned g_bar_count[2];
__device__ volatile unsigned g_bar_epoch[2];

// ---------------- helpers ----------------
__device__ __forceinline__ uint32_t smem_u32(const void* p) {
    uint32_t a;
    asm("{ .reg .u64 t; cvta.to.shared.u64 t, %1; cvt.u32.u64 %0, t; }" : "=r"(a) : "l"(p));
    return a;
}
__device__ __forceinline__ void cp16(uint32_t dst, const void* src) {
    asm volatile("cp.async.cg.shared.global [%0], [%1], 16;" :: "r"(dst), "l"(src));
}
__device__ __forceinline__ void cp_commit() { asm volatile("cp.async.commit_group;"); }
__device__ __forceinline__ void cp_wait0()  { asm volatile("cp.async.wait_group 0;"); }
__device__ __forceinline__ void cp_wait1()  { asm volatile("cp.async.wait_group 1;"); }

__device__ __forceinline__ void ldm_x4(uint32_t* r, uint32_t addr) {
    asm volatile("ldmatrix.sync.aligned.m8n8.x4.shared.b16 {%0,%1,%2,%3}, [%4];"
                 : "=r"(r[0]), "=r"(r[1]), "=r"(r[2]), "=r"(r[3]) : "r"(addr));
}
__device__ __forceinline__ void ldm_x2(uint32_t* r, uint32_t addr) {
    asm volatile("ldmatrix.sync.aligned.m8n8.x2.shared.b16 {%0,%1}, [%2];"
                 : "=r"(r[0]), "=r"(r[1]) : "r"(addr));
}
__device__ __forceinline__ void mma16816(float* c, const uint32_t* a, const uint32_t* b) {
    asm volatile("mma.sync.aligned.m16n8k16.row.col.f32.f16.f16.f32 "
                 "{%0,%1,%2,%3}, {%4,%5,%6,%7}, {%8,%9}, {%0,%1,%2,%3};"
                 : "+f"(c[0]), "+f"(c[1]), "+f"(c[2]), "+f"(c[3])
                 : "r"(a[0]), "r"(a[1]), "r"(a[2]), "r"(a[3]), "r"(b[0]), "r"(b[1]));
}

// ---------------- prep kernels ----------------
__global__ void zero_state_kernel() {
    int idx = blockIdx.x * blockDim.x + threadIdx.x;
    if (idx < 2 * 2 * BB * HH) {
        g_h_hi[idx] = __float2half(0.f);
        g_h_lo[idx] = __float2half(0.f);
    }
    if (idx < 2 * BB * HH) g_c[idx] = 0.0f;
    if (idx < 2) { g_bar_count[idx] = 0u; g_bar_epoch[idx] = 0u; }
}

__global__ void prep_x_kernel(const float* __restrict__ x) {
    size_t i = (size_t)blockIdx.x * blockDim.x + threadIdx.x;
    if (i >= (size_t)BB * SS * II) return;
    float v = x[i];
    __half h = __float2half_rn(v);
    g_x_hi[i] = h;
    g_x_lo[i] = __float2half_rn(v - __half2float(h));
}

// W[k][gc] -> Wt[dir][prow = j*4+gate][k], gc = gate*512 + j  (single fp16)
__global__ void prep_w_kernel(const float* __restrict__ W_f, const float* __restrict__ W_b) {
    int idx = blockIdx.x * blockDim.x + threadIdx.x;
    if (idx >= 2 * KTOT * G4) return;
    int dir = idx / (KTOT * G4);
    int rem = idx % (KTOT * G4);
    int k  = rem / G4;
    int gc = rem % G4;
    float w = (dir ? W_b : W_f)[rem];
    int gate = gc >> 9;
    int j    = gc & 511;
    int prow = j * 4 + gate;
    g_wt[((size_t)dir * G4 + prow) * KTOT + k] = __float2half_rn(w);
}

__global__ void prep_bias_kernel(const float* __restrict__ b_f, const float* __restrict__ b_b) {
    int idx = blockIdx.x * blockDim.x + threadIdx.x;
    if (idx >= 2 * G4) return;
    int dir = idx / G4;
    int gc  = idx % G4;
    int gate = gc >> 9, j = gc & 511;
    g_bias_p[dir * G4 + j * 4 + gate] = (dir ? b_b : b_f)[gc];
}

// ---------------- chunk loader (no commit) ----------------
__device__ __forceinline__ void load_chunk(uint32_t smb, int abuf, int ch,
                                           int tid, int dir, int p, int tx) {
    uint32_t base = smb + A_OFF + abuf * A_BUF;
    const int k0 = ch * KC;
#pragma unroll
    for (int i = 0; i < 2; i++) {
        int idx = tid + i * 256;
        int r = idx >> 3, q = idx & 7;
        uint32_t doff = r * RSTRIDE + q * 16;
        const __half *sh, *sl;
        if (k0 < II) {
            size_t so = ((size_t)r * SS + tx) * II + k0 + q * 8;
            sh = g_x_hi + so; sl = g_x_lo + so;
        } else {
            size_t so = ((size_t)(dir * 2 + p) * BB + r) * HH + (k0 - II) + q * 8;
            sh = g_h_hi + so; sl = g_h_lo + so;
        }
        cp16(base + doff, sh);
        cp16(base + 9216 + doff, sl);
    }
}

// ---------------- chunk compute: 2-term fp16 ----------------
__device__ __forceinline__ void compute_chunk(uint32_t smb, int abuf, int ch,
                                              int lane, int wm, int wn,
                                              float accH[2][4], float accX[2][4]) {
    const uint32_t Ab = smb + A_OFF + abuf * A_BUF;
    const uint32_t Bb = smb + B_OFF + (uint32_t)ch * 4608;
#pragma unroll
    for (int ks = 0; ks < 4; ks++) {
        uint32_t ah[4], al[4], bh[2][2];
        uint32_t ad = Ab + (uint32_t)(wm * 16 + (lane & 15)) * RSTRIDE
                         + (uint32_t)(ks * 16 + (lane >> 4) * 8) * 2;
        ldm_x4(ah, ad);
        ldm_x4(al, ad + 9216);
#pragma unroll
        for (int nt = 0; nt < 2; nt++) {
            uint32_t boff = (uint32_t)(wn * 16 + nt * 8 + (lane & 7)) * RSTRIDE
                          + (uint32_t)(ks * 16 + ((lane >> 3) & 1) * 8) * 2;
            ldm_x2(bh[nt], Bb + boff);
        }
#pragma unroll
        for (int nt = 0; nt < 2; nt++) {
            mma16816(accH[nt], ah, bh[nt]);
            mma16816(accX[nt], al, bh[nt]);
        }
    }
}

// ---------------- persistent kernel ----------------
__global__ void __launch_bounds__(256, 1) lstm_persistent(float* __restrict__ out) {
    extern __shared__ __align__(16) char sm[];
    const int tid  = threadIdx.x;
    const int lane = tid & 31;
    const int wid  = tid >> 5;
    const int wm   = wid & 3;
    const int wn   = wid >> 2;
    const int tile = blockIdx.x;
    const int dir  = blockIdx.y;
    const int n0 = tile * 32;
    const int j0 = tile * 8;
    const uint32_t smb = smem_u32(sm);

    const int frow = wm * 16 + (lane >> 2);
    const int fc0  = wn * 16 + 0 * 8 + 2 * (lane & 3);
    const int fc1  = wn * 16 + 1 * 8 + 2 * (lane & 3);

    // ---- all 12 weight chunks resident in smem (single fp16) ----
    for (int u = tid; u < NCH * 32 * 8; u += 256) {
        int ch = u >> 8;
        int rem = u & 255;
        int r = rem >> 3, q = rem & 7;
        size_t so = ((size_t)dir * G4 + n0 + r) * KTOT + ch * KC + q * 8;
        uint32_t doff = (uint32_t)ch * 4608 + r * RSTRIDE + q * 16;
        cp16(smb + B_OFF + doff, g_wt + so);
    }
    cp_commit();
    cp_wait0();
    __syncthreads();

    float2 bv0 = make_float2(g_bias_p[dir * G4 + n0 + fc0],
                             g_bias_p[dir * G4 + n0 + fc0 + 1]);
    float2 bv1 = make_float2(g_bias_p[dir * G4 + n0 + fc1],
                             g_bias_p[dir * G4 + n0 + fc1 + 1]);

    float* gx_cta = g_gx + ((size_t)(dir * NTILES + tile) * SS) * BB * 32;

    // ============ PHASE 1: x-part gates, timestep-granularity double buffer ====
    // stage s (0/1) = A buffers s*4 .. s*4+3; one commit group per timestep.
    {
        // prologue: t=0 -> stage0, t=1 -> stage1
#pragma unroll
        for (int ch = 0; ch < 4; ch++) load_chunk(smb, ch, ch, tid, dir, 0, 0);
        cp_commit();
#pragma unroll
        for (int ch = 0; ch < 4; ch++) load_chunk(smb, 4 + ch, ch, tid, dir, 0, 1);
        cp_commit();

#pragma unroll 1
        for (int t = 0; t < SS; t++) {
            if (t + 1 < SS) cp_wait1(); else cp_wait0();
            __syncthreads();

            float accH[2][4], accX[2][4];
#pragma unroll
            for (int nt = 0; nt < 2; nt++)
#pragma unroll
                for (int i = 0; i < 4; i++) { accH[nt][i] = 0.f; accX[nt][i] = 0.f; }

            const int st = (t & 1) * 4;
#pragma unroll
            for (int ch = 0; ch < 4; ch++)
                compute_chunk(smb, st + ch, ch, lane, wm, wn, accH, accX);

            float* gxt = gx_cta + (size_t)t * (BB * 32);
            *(float2*)&gxt[frow * 32 + fc0] =
                make_float2(accH[0][0] + accX[0][0] + bv0.x, accH[0][1] + accX[0][1] + bv0.y);
            *(float2*)&gxt[(frow + 8) * 32 + fc0] =
                make_float2(accH[0][2] + accX[0][2] + bv0.x, accH[0][3] + accX[0][3] + bv0.y);
            *(float2*)&gxt[frow * 32 + fc1] =
                make_float2(accH[1][0] + accX[1][0] + bv1.x, accH[1][1] + accX[1][1] + bv1.y);
            *(float2*)&gxt[(frow + 8) * 32 + fc1] =
                make_float2(accH[1][2] + accX[1][2] + bv1.x, accH[1][3] + accX[1][3] + bv1.y);

            __syncthreads();   // all warps done reading stage before refill
            if (t + 2 < SS) {
#pragma unroll
                for (int ch = 0; ch < 4; ch++)
                    load_chunk(smb, st + ch, ch, tid, dir, 0, t + 2);
                cp_commit();
            }
        }
    }

    // ============ PHASE 2: 512-step recurrence ============
#pragma unroll 1
    for (int t = 0; t < SS; t++) {
        const int tx = dir ? (SS - 1 - t) : t;
        const int p  = t & 1;

        // gx seed loads: issued before the barrier spin (independent of h)
        const float* gxt = gx_cta + (size_t)tx * (BB * 32);
        float2 s00 = *(const float2*)&gxt[frow * 32 + fc0];
        float2 s01 = *(const float2*)&gxt[(frow + 8) * 32 + fc0];
        float2 s10 = *(const float2*)&gxt[frow * 32 + fc1];
        float2 s11 = *(const float2*)&gxt[(frow + 8) * 32 + fc1];

        // barrier WAIT (per-direction): h(parity p) from step t-1 published
        if (t > 0) {
            if (tid == 0) {
                while (g_bar_epoch[dir] < (unsigned)t) {}
                __threadfence();
            }
            __syncthreads();
        }

        // issue ALL 8 h-chunk loads into dedicated buffers, one group
#pragma unroll
        for (int hc = 0; hc < 8; hc++)
            load_chunk(smb, hc, 4 + hc, tid, dir, p, tx);
        cp_commit();

        float accH[2][4], accX[2][4];
        accH[0][0] = s00.x; accH[0][1] = s00.y; accH[0][2] = s01.x; accH[0][3] = s01.y;
        accH[1][0] = s10.x; accH[1][1] = s10.y; accH[1][2] = s11.x; accH[1][3] = s11.y;
#pragma unroll
        for (int nt = 0; nt < 2; nt++)
#pragma unroll
            for (int i = 0; i < 4; i++) accX[nt][i] = 0.f;

        cp_wait0();
        __syncthreads();   // one sync; then 8 chunks of uninterrupted compute
#pragma unroll
        for (int hc = 0; hc < 8; hc++)
            compute_chunk(smb, hc, 4 + hc, lane, wm, wn, accH, accX);

        // ---- epilogue: gates to smem ----
        float* Gs = (float*)(sm + GS_OFF);   // [64][36]
        {
            int col0 = wn * 16 + 2 * (lane & 3);
            *(float2*)&Gs[frow * 36 + col0] =
                make_float2(accH[0][0] + accX[0][0], accH[0][1] + accX[0][1]);
            *(float2*)&Gs[(frow + 8) * 36 + col0] =
                make_float2(accH[0][2] + accX[0][2], accH[0][3] + accX[0][3]);
            *(float2*)&Gs[frow * 36 + col0 + 8] =
                make_float2(accH[1][0] + accX[1][0], accH[1][1] + accX[1][1]);
            *(float2*)&Gs[(frow + 8) * 36 + col0 + 8] =
                make_float2(accH[1][2] + accX[1][2], accH[1][3] + accX[1][3]);
        }
        __syncthreads();

        // ---- pointwise LSTM update (bias already in gx) ----
#pragma unroll
        for (int r2 = 0; r2 < 2; r2++) {
            int e = tid + r2 * 256;
            int b = e & 63;
            int jl = e >> 6;
            float4 g = *(float4*)&Gs[b * 36 + jl * 4];
            float fs = 1.0f / (1.0f + __expf(-g.x));
            float is = 1.0f / (1.0f + __expf(-g.y));
            float os = 1.0f / (1.0f + __expf(-g.z));
            int n = j0 + jl;
            float cprev = g_c[(dir * BB + b) * HH + n];
            float cn = fs * cprev + is * tanhf(g.w);
            float hn = os * tanhf(cn);
            g_c[(dir * BB + b) * HH + n] = cn;
            size_t hidx = ((size_t)(dir * 2 + (1 - p)) * BB + b) * HH + n;
            __half hh = __float2half_rn(hn);
            g_h_hi[hidx] = hh;
            g_h_lo[hidx] = __float2half_rn(hn - __half2float(hh));
            size_t oi = ((size_t)b * SS + tx) * HH + n;
            if (dir == 0) out[oi]  = 0.5f * hn;
            else          g_hb[oi] = 0.5f * hn;
        }

        // ---- barrier ARRIVE (per-direction) ----
        __syncthreads();
        if (t < SS - 1 && tid == 0) {
            __threadfence();
            unsigned n = atomicAdd(&g_bar_count[dir], 1u);
            if (n == NCTA_DIR - 1u) {
                g_bar_count[dir] = 0u;
                __threadfence();
                g_bar_epoch[dir] = (unsigned)(t + 1);
            }
        }
    }
}

// out = 0.5*hf + 0.5*hb
__global__ void combine_kernel(float* __restrict__ out) {
    size_t i = (size_t)blockIdx.x * blockDim.x + threadIdx.x;
    const size_t n4 = (size_t)BB * SS * HH / 4;
    if (i < n4) {
        float4 a = ((const float4*)out)[i];
        float4 b = ((const float4*)g_hb)[i];
        a.x += b.x; a.y += b.y; a.z += b.z; a.w += b.w;
        ((float4*)out)[i] = a;
    }
}

extern "C" void kernel_launch(void* const* d_in, const int* in_sizes, int n_in,
                              void* d_out, int out_size) {
    const float* x   = (const float*)d_in[0];
    const float* W_f = (const float*)d_in[1];
    const float* b_f = (const float*)d_in[2];
    const float* W_b = (const float*)d_in[3];
    const float* b_b = (const float*)d_in[4];
    float* out = (float*)d_out;

    cudaFuncSetAttribute((const void*)lstm_persistent,
                         cudaFuncAttributeMaxDynamicSharedMemorySize, SMEM_DYN);

    zero_state_kernel<<<512, 256>>>();
    {
        size_t nx = (size_t)BB * SS * II;
        prep_x_kernel<<<(unsigned)((nx + 255) / 256), 256>>>(x);
    }
    prep_w_kernel<<<(2 * KTOT * G4 + 255) / 256, 256>>>(W_f, W_b);
    prep_bias_kernel<<<(2 * G4 + 255) / 256, 256>>>(b_f, b_b);

    dim3 grid(NTILES, 2);
    lstm_persistent<<<grid, 256, SMEM_DYN>>>(out);

    const int n4 = BB * SS * HH / 4;
    combine_kernel<<<(n4 + 255) / 256, 256>>>(out);
}